// round 1
// baseline (speedup 1.0000x reference)
#include <cuda_runtime.h>
#include <cuda_bf16.h>
#include <math.h>

// Problem constants
#define BB 128
#define SS 1024
#define IND 256
#define DD 128
#define MM 64
#define OUTD 128
#define NROWS (BB * SS)   // 131072

// Scratch (device globals; no runtime allocation allowed)
// g_pack per (b,s): [0..64) w, [64..192) e, [192..320) a
__device__ float g_k[(size_t)NROWS * DD];
__device__ float g_pack[(size_t)NROWS * 320];
__device__ float g_r[(size_t)NROWS * DD];

// ---------------- f32x2 helpers (sm_100+ packed fp32) ----------------
__device__ __forceinline__ unsigned long long f2fma(unsigned long long a,
                                                    unsigned long long b,
                                                    unsigned long long c) {
    unsigned long long d;
    asm("fma.rn.f32x2 %0, %1, %2, %3;" : "=l"(d) : "l"(a), "l"(b), "l"(c));
    return d;
}
__device__ __forceinline__ unsigned long long f2add(unsigned long long a,
                                                    unsigned long long b) {
    unsigned long long d;
    asm("add.rn.f32x2 %0, %1, %2;" : "=l"(d) : "l"(a), "l"(b));
    return d;
}

// =====================================================================
// Kernel 1: projections.  blockIdx.y==0: k = x@Wr + br -> g_k
//                         blockIdx.y==1: v = x@Ww + bw -> e=sigmoid(v), a=tanh(v) -> g_pack
// 128x128 output tile per CTA, K=256, BK=16, 8x8 per thread.
// =====================================================================
__global__ __launch_bounds__(256) void proj_kernel(
    const float* __restrict__ x,
    const float* __restrict__ Wr, const float* __restrict__ br,
    const float* __restrict__ Ww, const float* __restrict__ bw) {
    const int KD = 256, BK = 16;
    __shared__ __align__(16) float As[16][132];
    __shared__ __align__(16) float Bs[16][128];

    const float* W    = blockIdx.y ? Ww : Wr;
    const float* bias = blockIdx.y ? bw : br;
    const int row0 = blockIdx.x * 128;
    const int t = threadIdx.x;
    const int tm = (t >> 4) * 8;
    const int tn = (t & 15) * 8;

    float acc[8][8];
#pragma unroll
    for (int i = 0; i < 8; i++)
#pragma unroll
        for (int j = 0; j < 8; j++) acc[i][j] = 0.f;

    for (int k0 = 0; k0 < KD; k0 += BK) {
        // A tile: x[row0..+128, k0..+16] -> As[k][m] (transposed store)
#pragma unroll
        for (int i = 0; i < 2; i++) {
            int idx = t + i * 256;            // 0..511
            int m  = idx >> 2;
            int kq = (idx & 3) * 4;
            float4 v = *(const float4*)(x + (size_t)(row0 + m) * KD + k0 + kq);
            As[kq + 0][m] = v.x; As[kq + 1][m] = v.y;
            As[kq + 2][m] = v.z; As[kq + 3][m] = v.w;
        }
        // B tile: W[k0..+16, 0..128] -> Bs[k][n]
#pragma unroll
        for (int i = 0; i < 2; i++) {
            int idx = t + i * 256;
            int kk = idx >> 5;
            int nq = (idx & 31) * 4;
            *(float4*)&Bs[kk][nq] = *(const float4*)(W + (size_t)(k0 + kk) * 128 + nq);
        }
        __syncthreads();
#pragma unroll
        for (int kk = 0; kk < BK; kk++) {
            float a[8], b[8];
            *(float4*)(a)     = *(const float4*)&As[kk][tm];
            *(float4*)(a + 4) = *(const float4*)&As[kk][tm + 4];
            *(float4*)(b)     = *(const float4*)&Bs[kk][tn];
            *(float4*)(b + 4) = *(const float4*)&Bs[kk][tn + 4];
#pragma unroll
            for (int i = 0; i < 8; i++)
#pragma unroll
                for (int j = 0; j < 8; j++) acc[i][j] = fmaf(a[i], b[j], acc[i][j]);
        }
        __syncthreads();
    }

    float bb[8];
    *(float4*)(bb)     = *(const float4*)(bias + tn);
    *(float4*)(bb + 4) = *(const float4*)(bias + tn + 4);

    if (blockIdx.y == 0) {
#pragma unroll
        for (int i = 0; i < 8; i++) {
            size_t row = (size_t)(row0 + tm + i);
            float o[8];
#pragma unroll
            for (int j = 0; j < 8; j++) o[j] = acc[i][j] + bb[j];
            *(float4*)(g_k + row * DD + tn)     = *(float4*)(o);
            *(float4*)(g_k + row * DD + tn + 4) = *(float4*)(o + 4);
        }
    } else {
#pragma unroll
        for (int i = 0; i < 8; i++) {
            size_t row = (size_t)(row0 + tm + i);
            float e[8], av[8];
#pragma unroll
            for (int j = 0; j < 8; j++) {
                float v = acc[i][j] + bb[j];
                e[j]  = 1.0f / (1.0f + expf(-v));
                av[j] = tanhf(v);
            }
            float* pr = g_pack + row * 320;
            *(float4*)(pr + 64 + tn)      = *(float4*)(e);
            *(float4*)(pr + 64 + tn + 4)  = *(float4*)(e + 4);
            *(float4*)(pr + 192 + tn)     = *(float4*)(av);
            *(float4*)(pr + 192 + tn + 4) = *(float4*)(av + 4);
        }
    }
}

// =====================================================================
// Kernel 2: attention weights. w = softmax(k @ MK^T) -> g_pack[row][0..64)
// 16 rows per CTA (2 rows per warp), MK in SMEM, per-lane 2 m's.
// =====================================================================
__global__ __launch_bounds__(256) void attw_kernel(const float* __restrict__ mk) {
    __shared__ __align__(16) float smk[64][132];
    __shared__ __align__(16) float sk[16][128];
    const int t = threadIdx.x;
    const size_t row0 = (size_t)blockIdx.x * 16;

    for (int i = t; i < 64 * 32; i += 256) {
        int m = i >> 5, q = (i & 31) * 4;
        *(float4*)&smk[m][q] = *(const float4*)(mk + m * 128 + q);
    }
    for (int i = t; i < 16 * 32; i += 256) {
        int r = i >> 5, q = (i & 31) * 4;
        *(float4*)&sk[r][q] = *(const float4*)(g_k + (row0 + r) * DD + q);
    }
    __syncthreads();

    const int w = t >> 5, lane = t & 31;
    float acc[2][2] = {{0.f, 0.f}, {0.f, 0.f}};  // [m-slot][row]
#pragma unroll
    for (int c = 0; c < 4; c++) {
        float4 mr0[8], mr1[8];
#pragma unroll
        for (int q = 0; q < 8; q++) {
            mr0[q] = *(const float4*)&smk[lane][(c * 8 + q) * 4];
            mr1[q] = *(const float4*)&smk[lane + 32][(c * 8 + q) * 4];
        }
#pragma unroll
        for (int r = 0; r < 2; r++) {
#pragma unroll
            for (int q = 0; q < 8; q++) {
                float4 kv = *(const float4*)&sk[w * 2 + r][(c * 8 + q) * 4];
                acc[0][r] += mr0[q].x * kv.x + mr0[q].y * kv.y + mr0[q].z * kv.z + mr0[q].w * kv.w;
                acc[1][r] += mr1[q].x * kv.x + mr1[q].y * kv.y + mr1[q].z * kv.z + mr1[q].w * kv.w;
            }
        }
    }

#pragma unroll
    for (int r = 0; r < 2; r++) {
        float v0 = acc[0][r], v1 = acc[1][r];
        float mx = fmaxf(v0, v1);
#pragma unroll
        for (int o = 16; o > 0; o >>= 1) mx = fmaxf(mx, __shfl_xor_sync(0xffffffffu, mx, o));
        float e0 = expf(v0 - mx), e1 = expf(v1 - mx);
        float sm = e0 + e1;
#pragma unroll
        for (int o = 16; o > 0; o >>= 1) sm += __shfl_xor_sync(0xffffffffu, sm, o);
        float inv = 1.0f / sm;
        float* dst = g_pack + (row0 + w * 2 + r) * 320;
        dst[lane]      = e0 * inv;
        dst[lane + 32] = e1 * inv;
    }
}

// =====================================================================
// Kernel 3: sequential scan. One CTA per batch. Mv[64][128] in registers:
// thread t: d-pair dp=t>>2 (d=2dp,2dp+1), m-range [16*(t&3), +16).
// Per step: r[d]=sum_m w[m]*Mv ; Mv += w[m]*(a[d]-e[d]*Mv).  f32x2 FMAs.
// w/e/a streamed from g_pack in chunks of 4 steps, double buffered.
// SMEM per step slot: [0..128) w duplicated, [128..256) e, [256..384) a.
// =====================================================================
__device__ __forceinline__ void stage_store(float (*buf)[384], const float* v) {
    const int t = threadIdx.x;
#pragma unroll
    for (int k = 0; k < 5; k++) {
        int idx = t + 256 * k;           // 0..1279
        int q = idx / 320;
        int j = idx - q * 320;
        if (j < 64) { buf[q][2 * j] = v[k]; buf[q][2 * j + 1] = v[k]; }
        else        { buf[q][64 + j] = v[k]; }
    }
}

__global__ __launch_bounds__(256) void scan_kernel(const float* __restrict__ mv0,
                                                   float* __restrict__ rout) {
    __shared__ __align__(16) float sbuf[2][4][384];
    const int b  = blockIdx.x;
    const int t  = threadIdx.x;
    const int dp = t >> 2;
    const int mq = t & 3;
    const int m0 = mq * 16;

    unsigned long long Mv[16];
#pragma unroll
    for (int i = 0; i < 16; i++)
        Mv[i] = *(const unsigned long long*)(mv0 + (m0 + i) * 128 + 2 * dp);

    const float* pk = g_pack + (size_t)b * (SS * 320);
    float stg[5];
#pragma unroll
    for (int k = 0; k < 5; k++) stg[k] = pk[t + 256 * k];
    stage_store(sbuf[0], stg);
    __syncthreads();

    float* rb = rout + (size_t)b * (SS * 128) + 2 * dp;
    const int NCHUNK = SS / 4;

    for (int c = 0; c < NCHUNK; c++) {
        const int pb = c & 1;
        const bool more = (c + 1 < NCHUNK);
        if (more) {
            const float* pn = pk + (size_t)(c + 1) * 1280;
#pragma unroll
            for (int k = 0; k < 5; k++) stg[k] = pn[t + 256 * k];
        }
#pragma unroll
        for (int q = 0; q < 4; q++) {
            const float* bq = sbuf[pb][q];
            unsigned long long e2 = *(const unsigned long long*)(bq + 128 + 2 * dp);
            unsigned long long a2 = *(const unsigned long long*)(bq + 256 + 2 * dp);
            unsigned long long ne2 = e2 ^ 0x8000000080000000ULL;
            unsigned long long r2a = 0ULL, r2b = 0ULL;
#pragma unroll
            for (int i = 0; i < 16; i += 2) {
                ulonglong2 ww = *(const ulonglong2*)(bq + 2 * (m0 + i));
                r2a = f2fma(ww.x, Mv[i], r2a);                 // r += w*Mv (old Mv)
                unsigned long long t0 = f2fma(ne2, Mv[i], a2); // a - e*Mv
                Mv[i] = f2fma(ww.x, t0, Mv[i]);                // Mv += w*(a - e*Mv)
                r2b = f2fma(ww.y, Mv[i + 1], r2b);
                unsigned long long t1 = f2fma(ne2, Mv[i + 1], a2);
                Mv[i + 1] = f2fma(ww.y, t1, Mv[i + 1]);
            }
            unsigned long long r2 = f2add(r2a, r2b);
            float rx = __uint_as_float((unsigned)(r2 & 0xffffffffu));
            float ry = __uint_as_float((unsigned)(r2 >> 32));
            rx += __shfl_xor_sync(0xffffffffu, rx, 1);
            ry += __shfl_xor_sync(0xffffffffu, ry, 1);
            rx += __shfl_xor_sync(0xffffffffu, rx, 2);
            ry += __shfl_xor_sync(0xffffffffu, ry, 2);
            if (mq == 0) {
                float2 rv; rv.x = rx; rv.y = ry;
                *(float2*)(rb + (size_t)(c * 4 + q) * 128) = rv;
            }
        }
        if (more) stage_store(sbuf[pb ^ 1], stg);
        __syncthreads();
    }
}

// =====================================================================
// Kernel 4: y = sigmoid(r @ Wp + bp) -> out.  [131072,128]@[128,128].
// =====================================================================
__global__ __launch_bounds__(256) void out_kernel(const float* __restrict__ Wp,
                                                  const float* __restrict__ bp,
                                                  float* __restrict__ out) {
    const int KD = 128, BK = 16;
    __shared__ __align__(16) float As[16][132];
    __shared__ __align__(16) float Bs[16][128];
    const int row0 = blockIdx.x * 128;
    const int t = threadIdx.x;
    const int tm = (t >> 4) * 8;
    const int tn = (t & 15) * 8;

    float acc[8][8];
#pragma unroll
    for (int i = 0; i < 8; i++)
#pragma unroll
        for (int j = 0; j < 8; j++) acc[i][j] = 0.f;

    for (int k0 = 0; k0 < KD; k0 += BK) {
#pragma unroll
        for (int i = 0; i < 2; i++) {
            int idx = t + i * 256;
            int m  = idx >> 2;
            int kq = (idx & 3) * 4;
            float4 v = *(const float4*)(g_r + (size_t)(row0 + m) * KD + k0 + kq);
            As[kq + 0][m] = v.x; As[kq + 1][m] = v.y;
            As[kq + 2][m] = v.z; As[kq + 3][m] = v.w;
        }
#pragma unroll
        for (int i = 0; i < 2; i++) {
            int idx = t + i * 256;
            int kk = idx >> 5;
            int nq = (idx & 31) * 4;
            *(float4*)&Bs[kk][nq] = *(const float4*)(Wp + (size_t)(k0 + kk) * 128 + nq);
        }
        __syncthreads();
#pragma unroll
        for (int kk = 0; kk < BK; kk++) {
            float a[8], b[8];
            *(float4*)(a)     = *(const float4*)&As[kk][tm];
            *(float4*)(a + 4) = *(const float4*)&As[kk][tm + 4];
            *(float4*)(b)     = *(const float4*)&Bs[kk][tn];
            *(float4*)(b + 4) = *(const float4*)&Bs[kk][tn + 4];
#pragma unroll
            for (int i = 0; i < 8; i++)
#pragma unroll
                for (int j = 0; j < 8; j++) acc[i][j] = fmaf(a[i], b[j], acc[i][j]);
        }
        __syncthreads();
    }

    float bb[8];
    *(float4*)(bb)     = *(const float4*)(bp + tn);
    *(float4*)(bb + 4) = *(const float4*)(bp + tn + 4);
#pragma unroll
    for (int i = 0; i < 8; i++) {
        size_t row = (size_t)(row0 + tm + i);
        float o[8];
#pragma unroll
        for (int j = 0; j < 8; j++) {
            float v = acc[i][j] + bb[j];
            o[j] = 1.0f / (1.0f + expf(-v));
        }
        *(float4*)(out + row * OUTD + tn)     = *(float4*)(o);
        *(float4*)(out + row * OUTD + tn + 4) = *(float4*)(o + 4);
    }
}

// =====================================================================
// Launch
// =====================================================================
extern "C" void kernel_launch(void* const* d_in, const int* in_sizes, int n_in,
                              void* d_out, int out_size) {
    const float* x   = (const float*)d_in[0];
    const float* mk  = (const float*)d_in[1];
    const float* mv  = (const float*)d_in[2];
    const float* Wr  = (const float*)d_in[3];
    const float* br  = (const float*)d_in[4];
    const float* Ww  = (const float*)d_in[5];
    const float* bw  = (const float*)d_in[6];
    const float* Wp  = (const float*)d_in[7];
    const float* bp  = (const float*)d_in[8];
    float* out = (float*)d_out;

    float* gr;
    cudaGetSymbolAddress((void**)&gr, g_r);

    proj_kernel<<<dim3(NROWS / 128, 2), 256>>>(x, Wr, br, Ww, bw);
    attw_kernel<<<NROWS / 16, 256>>>(mk);
    scan_kernel<<<BB, 256>>>(mv, gr);
    out_kernel<<<NROWS / 128, 256>>>(Wp, bp, out);
}